// round 3
// baseline (speedup 1.0000x reference)
#include <cuda_runtime.h>
#include <math.h>
#include <stdint.h>

#define B_   16
#define CIN_ 512
#define COUT_ 512
#define HIN_ 32
#define WIN_ 32
#define HOUT_ 64
#define WOUT_ 64

// ---------------- device scratch (static __device__ globals: allowed) -------------
__device__ float g_s1[B_ * CIN_];
__device__ float g_s2[B_ * COUT_];
__device__ float g_sr[B_ * COUT_];
__device__ float g_d[2][B_ * COUT_];
__device__ float g_A[2][CIN_ * COUT_];
__device__ float g_wr3[3 * COUT_];
__device__ float g_ydc[(size_t)B_ * HOUT_ * WOUT_ * COUT_]; // deconv out (pre-blur)
__device__ float g_x1[(size_t)B_ * HOUT_ * WOUT_ * COUT_];  // style block 1 out

static __constant__ float kFclScale = 0.04419417382415922f;   // 1/sqrt(512)
static __constant__ float kWs9      = 0.014731391274719738f;  // 1/sqrt(4608)

// ---------------- small kernels ---------------------------------------------------

// s = w @ (fw * 1/sqrt(512)) + fb   -> sout[b*512 + c]
__global__ void fcl_kernel(const float* __restrict__ w, const float* __restrict__ fw,
                           const float* __restrict__ fb, float* __restrict__ sout) {
    __shared__ float wsh[512];
    int b = blockIdx.x, c = threadIdx.x;
    wsh[c] = w[b * 512 + c];
    __syncthreads();
    float acc = 0.f;
#pragma unroll 8
    for (int k = 0; k < 512; ++k) acc += wsh[k] * fw[k * 512 + c];
    sout[b * 512 + c] = acc * kFclScale + fb[c];
}

// A[sel][cin][cout] = wscale^2 * sum_t w[t,cin,cout]^2
__global__ void a_kernel(const float* __restrict__ w1, const float* __restrict__ w2) {
    int cin = blockIdx.x, sel = blockIdx.y, c = threadIdx.x;
    const float* w = sel ? w2 : w1;
    float acc = 0.f;
#pragma unroll
    for (int t = 0; t < 9; ++t) {
        float v = w[((size_t)t * 512 + cin) * 512 + c];
        acc += v * v;
    }
    g_A[sel][cin * 512 + c] = acc * (1.0f / 4608.0f);
}

// d[sel][b][cout] = rsqrt( sum_cin A[cin][cout]*s^2 + 1e-8 )
__global__ void d_kernel() {
    __shared__ float ssq[512];
    int b = blockIdx.x, sel = blockIdx.y, c = threadIdx.x;
    const float* s = sel ? g_s2 : g_s1;
    float sv = s[b * 512 + c];
    ssq[c] = sv * sv;
    __syncthreads();
    float acc = 0.f;
#pragma unroll 8
    for (int k = 0; k < 512; ++k) acc += g_A[sel][k * 512 + c] * ssq[k];
    g_d[sel][b * 512 + c] = rsqrtf(acc + 1e-8f);
}

// wr3[j][c] = convr_w[c][j] / sqrt(512)
__global__ void wr3_kernel(const float* __restrict__ wr) {
    int c = threadIdx.x;
#pragma unroll
    for (int j = 0; j < 3; ++j) g_wr3[j * 512 + c] = wr[c * 3 + j] * kFclScale;
}

// ---------------- tiled implicit-GEMM conv ---------------------------------------
// out[b, a*ymul+yadd, p*xmul+xadd, cout0..+256) +=
//   sum over taps t, cin:  xin[b, a+dy, p+dx, cin]*s[b,cin] * wt[wi][cin][cout]*wscale
// Fused epilogue if dvec != null: v = acc*d + snoise*noise + bias; lrelu.
struct TapList { int n; int dy[9]; int dx[9]; int wi[9]; };

template <int TM>
__global__ __launch_bounds__(TM * 4)
void conv_mod_kernel(const float* __restrict__ xin, int Hin, int Win,
                     const float* __restrict__ wt, float wscale,
                     const float* __restrict__ svec, TapList taps, int Hrows,
                     int ymul, int yadd, int xmul, int xadd,
                     float* __restrict__ out,
                     const float* __restrict__ dvec, const float* __restrict__ noise,
                     const float* __restrict__ snoise, const float* __restrict__ bias) {
    constexpr int NT = TM * 4;
    constexpr int KC = 16;
    constexpr int TN = 256;
    constexpr int CSTR = NT / 64;
    __shared__ float xs[KC][TM];
    __shared__ float ws[KC][TN];

    const int tid = threadIdx.x;
    const int b = blockIdx.y / Hrows;
    const int a = blockIdx.y % Hrows;
    const int cout0 = blockIdx.x * TN;

    const int pr = tid % (TM / 8);
    const int jr = tid / (TM / 8);
    const int p0 = pr * 8, j0 = jr * 8;

    const int lpx = tid % TM;
    const int lc0 = (tid / TM) * 4;

    const int jw = (tid & 63) * 4;
    const int cw = tid >> 6;

    float acc[8][8];
#pragma unroll
    for (int i = 0; i < 8; ++i)
#pragma unroll
        for (int j = 0; j < 8; ++j) acc[i][j] = 0.f;

    const float* sb = svec + b * CIN_;

    for (int t = 0; t < taps.n; ++t) {
        const int dy = taps.dy[t], dx = taps.dx[t];
        const int iy = a + dy;
        const int ix = lpx + dx;
        const bool ok = (iy >= 0) && (iy < Hin) && (ix >= 0) && (ix < Win);
        const float* xptr = ok ? (xin + (((size_t)(b * Hin + iy)) * Win + ix) * CIN_ + lc0)
                               : xin;
        const float* wpl = wt + (size_t)taps.wi[t] * CIN_ * COUT_;

        for (int ck = 0; ck < CIN_; ck += KC) {
            __syncthreads();
            // fill xs (modulated, shifted, zero-padded)
            {
                float4 v = make_float4(0.f, 0.f, 0.f, 0.f);
                if (ok) {
                    v = *(const float4*)(xptr + ck);
                    float4 sm = *(const float4*)(sb + ck + lc0);
                    v.x *= sm.x; v.y *= sm.y; v.z *= sm.z; v.w *= sm.w;
                }
                xs[lc0 + 0][lpx] = v.x; xs[lc0 + 1][lpx] = v.y;
                xs[lc0 + 2][lpx] = v.z; xs[lc0 + 3][lpx] = v.w;
            }
            // fill ws (scaled)
#pragma unroll
            for (int i = 0; i < KC / CSTR; ++i) {
                int c = cw + i * CSTR;
                float4 wv = *(const float4*)(wpl + (size_t)(ck + c) * COUT_ + cout0 + jw);
                wv.x *= wscale; wv.y *= wscale; wv.z *= wscale; wv.w *= wscale;
                *(float4*)&ws[c][jw] = wv;
            }
            __syncthreads();

#pragma unroll
            for (int c = 0; c < KC; ++c) {
                float xv[8], wv[8];
                *(float4*)&xv[0] = *(const float4*)&xs[c][p0];
                *(float4*)&xv[4] = *(const float4*)&xs[c][p0 + 4];
                *(float4*)&wv[0] = *(const float4*)&ws[c][j0];
                *(float4*)&wv[4] = *(const float4*)&ws[c][j0 + 4];
#pragma unroll
                for (int i = 0; i < 8; ++i)
#pragma unroll
                    for (int j = 0; j < 8; ++j) acc[i][j] += xv[i] * wv[j];
            }
        }
    }

    const int oy = a * ymul + yadd;
    if (dvec) {
        float dv[8], sn[8], bi[8];
#pragma unroll
        for (int j = 0; j < 8; ++j) {
            int co = cout0 + j0 + j;
            dv[j] = dvec[b * COUT_ + co];
            sn[j] = snoise[co];
            bi[j] = bias[co];
        }
#pragma unroll
        for (int i = 0; i < 8; ++i) {
            int ox = (p0 + i) * xmul + xadd;
            float nz = noise[((size_t)b * HOUT_ + oy) * WOUT_ + ox];
            float* optr = out + (((size_t)b * HOUT_ + oy) * WOUT_ + ox) * COUT_ + cout0 + j0;
            float o[8];
#pragma unroll
            for (int j = 0; j < 8; ++j) {
                float v = acc[i][j] * dv[j] + sn[j] * nz + bi[j];
                o[j] = v >= 0.f ? v : 0.2f * v;
            }
            *(float4*)optr = *(float4*)&o[0];
            *(float4*)(optr + 4) = *(float4*)&o[4];
        }
    } else {
#pragma unroll
        for (int i = 0; i < 8; ++i) {
            int ox = (p0 + i) * xmul + xadd;
            float* optr = out + (((size_t)b * HOUT_ + oy) * WOUT_ + ox) * COUT_ + cout0 + j0;
            *(float4*)optr = *(float4*)&acc[i][0];
            *(float4*)(optr + 4) = *(float4*)&acc[i][4];
        }
    }
}

// ---------------- blur (4x4 separable) + demod + noise + bias + lrelu -------------
// f = [1,3,3,1]/8, gain 4 folded: fh = fv = [0.25, 0.75, 0.75, 0.25]
__global__ void blur_kernel(const float* __restrict__ ydc, float* __restrict__ x1out,
                            const float* __restrict__ noise, const float* __restrict__ snoise,
                            const float* __restrict__ bias) {
    const int cg = threadIdx.x & 127;
    const int c = cg * 4;
    const int xi = (blockIdx.x % 32) * 2 + (threadIdx.x >> 7);
    const int b = blockIdx.x / 32;

    const float F[4] = {0.25f, 0.75f, 0.75f, 0.25f};

    float4 dvv = *(const float4*)(&g_d[0][b * 512 + c]);
    float4 snv = *(const float4*)(snoise + c);
    float4 biv = *(const float4*)(bias + c);

    auto hrow = [&](int v) -> float4 {
        float4 r = make_float4(0.f, 0.f, 0.f, 0.f);
        if (v < 0 || v >= 64) return r;
        const float* base = ydc + (((size_t)b * 64 + v) * 64) * 512 + c;
#pragma unroll
        for (int u = 0; u < 4; ++u) {
            int xx = xi + u - 1;
            if (xx >= 0 && xx < 64) {
                float4 t = *(const float4*)(base + (size_t)xx * 512);
                float fw = F[u];
                r.x += fw * t.x; r.y += fw * t.y; r.z += fw * t.z; r.w += fw * t.w;
            }
        }
        return r;
    };

    float4 h0 = make_float4(0.f, 0.f, 0.f, 0.f);
    float4 h1 = hrow(0);
    float4 h2 = hrow(1);
    for (int y = 0; y < 64; ++y) {
        float4 h3 = hrow(y + 2);
        float4 o;
        o.x = 0.25f * h0.x + 0.75f * h1.x + 0.75f * h2.x + 0.25f * h3.x;
        o.y = 0.25f * h0.y + 0.75f * h1.y + 0.75f * h2.y + 0.25f * h3.y;
        o.z = 0.25f * h0.z + 0.75f * h1.z + 0.75f * h2.z + 0.25f * h3.z;
        o.w = 0.25f * h0.w + 0.75f * h1.w + 0.75f * h2.w + 0.25f * h3.w;
        float nz = noise[((size_t)b * 64 + y) * 64 + xi];
        float4 v;
        v.x = o.x * dvv.x + snv.x * nz + biv.x;
        v.y = o.y * dvv.y + snv.y * nz + biv.y;
        v.z = o.z * dvv.z + snv.z * nz + biv.z;
        v.w = o.w * dvv.w + snv.w * nz + biv.w;
        v.x = v.x >= 0.f ? v.x : 0.2f * v.x;
        v.y = v.y >= 0.f ? v.y : 0.2f * v.y;
        v.z = v.z >= 0.f ? v.z : 0.2f * v.z;
        v.w = v.w >= 0.f ? v.w : 0.2f * v.w;
        *(float4*)(x1out + (((size_t)b * 64 + y) * 64 + xi) * 512 + c) = v;
        h0 = h1; h1 = h2; h2 = h3;
    }
}

// ---------------- toRGB: 1x1 modulated conv (no demod) + bias + lrelu -------------
__global__ void torgb_kernel(const float* __restrict__ x2, float* __restrict__ rgb,
                             const float* __restrict__ biasr) {
    const int warp = threadIdx.x >> 5, lane = threadIdx.x & 31;
    const int pix = blockIdx.x * 8 + warp;   // [0, 16*4096)
    const int b = pix >> 12;
    const float* xp = x2 + (size_t)pix * 512;
    const float* sp = g_sr + b * 512;
    float r0 = 0.f, r1 = 0.f, r2 = 0.f;
#pragma unroll
    for (int k = 0; k < 4; ++k) {
        int c = lane * 4 + k * 128;
        float4 xv = *(const float4*)(xp + c);
        float4 sv = *(const float4*)(sp + c);
        xv.x *= sv.x; xv.y *= sv.y; xv.z *= sv.z; xv.w *= sv.w;
        float4 w0 = *(const float4*)(g_wr3 + 0 * 512 + c);
        float4 w1 = *(const float4*)(g_wr3 + 1 * 512 + c);
        float4 w2 = *(const float4*)(g_wr3 + 2 * 512 + c);
        r0 += xv.x * w0.x + xv.y * w0.y + xv.z * w0.z + xv.w * w0.w;
        r1 += xv.x * w1.x + xv.y * w1.y + xv.z * w1.z + xv.w * w1.w;
        r2 += xv.x * w2.x + xv.y * w2.y + xv.z * w2.z + xv.w * w2.w;
    }
#pragma unroll
    for (int off = 16; off > 0; off >>= 1) {
        r0 += __shfl_xor_sync(0xffffffffu, r0, off);
        r1 += __shfl_xor_sync(0xffffffffu, r1, off);
        r2 += __shfl_xor_sync(0xffffffffu, r2, off);
    }
    if (lane == 0) {
        float v0 = r0 + biasr[0];
        float v1 = r1 + biasr[1];
        float v2 = r2 + biasr[2];
        rgb[(size_t)pix * 3 + 0] = v0 >= 0.f ? v0 : 0.2f * v0;
        rgb[(size_t)pix * 3 + 1] = v1 >= 0.f ? v1 : 0.2f * v1;
        rgb[(size_t)pix * 3 + 2] = v2 >= 0.f ? v2 : 0.2f * v2;
    }
}

// ---------------- launch ----------------------------------------------------------
extern "C" void kernel_launch(void* const* d_in, const int* in_sizes, int n_in,
                              void* d_out, int out_size) {
    const float* x       = (const float*)d_in[0];
    const float* w       = (const float*)d_in[1];
    const float* noise1  = (const float*)d_in[2];
    const float* noise2  = (const float*)d_in[3];
    const float* fcl1_w  = (const float*)d_in[4];
    const float* fcl1_b  = (const float*)d_in[5];
    const float* conv1_w = (const float*)d_in[6];
    const float* sn1     = (const float*)d_in[7];
    const float* bias1   = (const float*)d_in[8];
    const float* fcl2_w  = (const float*)d_in[9];
    const float* fcl2_b  = (const float*)d_in[10];
    const float* conv2_w = (const float*)d_in[11];
    const float* sn2     = (const float*)d_in[12];
    const float* bias2   = (const float*)d_in[13];
    const float* fclr_w  = (const float*)d_in[14];
    const float* fclr_b  = (const float*)d_in[15];
    const float* convr_w = (const float*)d_in[16];
    const float* biasr   = (const float*)d_in[17];

    float* x2out  = (float*)d_out;
    float* rgbout = x2out + (size_t)B_ * HOUT_ * WOUT_ * COUT_;

    float *s1, *s2, *sr, *dd, *ydc, *x1;
    cudaGetSymbolAddress((void**)&s1, g_s1);
    cudaGetSymbolAddress((void**)&s2, g_s2);
    cudaGetSymbolAddress((void**)&sr, g_sr);
    cudaGetSymbolAddress((void**)&dd, g_d);
    cudaGetSymbolAddress((void**)&ydc, g_ydc);
    cudaGetSymbolAddress((void**)&x1, g_x1);
    float* d1 = dd;               // g_d[0]
    float* d2 = dd + B_ * COUT_;  // g_d[1]

    // styles + demod + toRGB weight prep
    fcl_kernel<<<B_, 512>>>(w, fcl1_w, fcl1_b, s1);
    fcl_kernel<<<B_, 512>>>(w, fcl2_w, fcl2_b, s2);
    fcl_kernel<<<B_, 512>>>(w, fclr_w, fclr_b, sr);
    a_kernel<<<dim3(512, 2), 512>>>(conv1_w, conv2_w);
    d_kernel<<<dim3(B_, 2), 512>>>();
    wr3_kernel<<<1, 512>>>(convr_w);

    const float WS9 = 0.014731391274719738f; // 1/sqrt(4608)

    // deconv (conv_transpose stride 2, SAME => pad (2,1)): 4 parity classes.
    // even out-row: taps kh={0,2} at ih={a-1,a}; odd: kh=1 at ih=a. Same for cols.
    for (int rh = 0; rh < 2; ++rh) {
        for (int rw = 0; rw < 2; ++rw) {
            TapList tl;
            int n = 0;
            const int khs0[2] = {0, 2};
            int nkh = rh ? 1 : 2;
            int nkw = rw ? 1 : 2;
            for (int ih = 0; ih < nkh; ++ih) {
                int kh = rh ? 1 : khs0[ih];
                int dy = (kh == 0) ? -1 : 0;
                for (int iw = 0; iw < nkw; ++iw) {
                    int kw = rw ? 1 : khs0[iw];
                    int dx = (kw == 0) ? -1 : 0;
                    tl.dy[n] = dy; tl.dx[n] = dx; tl.wi[n] = kh * 3 + kw; ++n;
                }
            }
            tl.n = n;
            conv_mod_kernel<32><<<dim3(2, B_ * 32), 128>>>(
                x, HIN_, WIN_, conv1_w, WS9, s1, tl, 32,
                2, rh, 2, rw, ydc, nullptr, nullptr, nullptr, nullptr);
        }
    }

    // blur + demod1 + noise1 + bias1 + lrelu -> g_x1
    blur_kernel<<<B_ * 32, 256>>>(ydc, x1, noise1, sn1, bias1);

    // conv2 (3x3 SAME) fused epilogue -> x2 (d_out)
    {
        TapList tl;
        tl.n = 9;
        for (int kh = 0; kh < 3; ++kh)
            for (int kw = 0; kw < 3; ++kw) {
                int t = kh * 3 + kw;
                tl.dy[t] = kh - 1; tl.dx[t] = kw - 1; tl.wi[t] = t;
            }
        conv_mod_kernel<64><<<dim3(2, B_ * 64), 256>>>(
            x1, HOUT_, WOUT_, conv2_w, WS9, s2, tl, 64,
            1, 0, 1, 0, x2out, d2, noise2, sn2, bias2);
    }

    // toRGB -> rgb (d_out tail)
    torgb_kernel<<<(B_ * HOUT_ * WOUT_) / 8, 256>>>(x2out, rgbout, biasr);
}